// round 7
// baseline (speedup 1.0000x reference)
#include <cuda_runtime.h>
#include <math.h>
#include <stdint.h>

#define N 512
#define N2 (N*N)
#define BATCH 128
#define NMAT 129           // 128 batch matrices + 1 for L0
#define EPSF 1e-7f
#define NPAN 16

typedef unsigned long long u64;

// packed f32x2 FMA (Blackwell FFMA2 — only reachable via PTX)
__device__ __forceinline__ u64 ffma2(u64 a, u64 b, u64 c) {
    u64 d;
    asm("fma.rn.f32x2 %0, %1, %2, %3;" : "=l"(d) : "l"(a), "l"(b), "l"(c));
    return d;
}
__device__ __forceinline__ u64 pack_dup(float a) {
    u64 d; unsigned int u = __float_as_uint(a);
    asm("mov.b64 %0, {%1, %1};" : "=l"(d) : "r"(u));
    return d;
}

// ---------------- device scratch (no allocations allowed) ----------------
__device__ float g_C[4 * N2];                                   // 4 planes, 4 MB
__device__ __align__(16) float g_M[(size_t)NMAT * N2 + 64];     // 129 matrices
__device__ __align__(16) float g_Lp[(size_t)NMAT * 32 * N];     // -L21, [mat][k*512+r]
__device__ __align__(16) float g_Up[(size_t)NMAT * 32 * N];     // +U12, [mat][k*512+c]
__device__ float g_ld[NMAT * NPAN];                             // per-panel logdet

// ---------------- kernel 1: IPF + plane construction ----------------
__global__ void k_ipf(const float* __restrict__ W, const float* __restrict__ Vc,
                      const float* __restrict__ Ec) {
    int p = blockIdx.x * blockDim.x + threadIdx.x;
    int i = p >> 9;
    int j = p & (N - 1);

    float4 e4 = reinterpret_cast<const float4*>(Ec)[p];
    float e00 = expf(e4.x), e01 = expf(e4.y), e10 = expf(e4.z), e11 = expf(e4.w);
    float inv = 1.0f / (e00 + e01 + e10 + e11);
    e00 *= inv; e01 *= inv; e10 *= inv; e11 *= inv;

    float a0 = Vc[2*i], a1 = Vc[2*i+1];
    float mi = fmaxf(a0, a1);
    float xa0 = expf(a0 - mi), xa1 = expf(a1 - mi);
    float di = 1.0f / (xa0 + xa1);
    float vi0 = xa0 * di, vi1 = xa1 * di;

    float b0 = Vc[2*j], b1 = Vc[2*j+1];
    float mj = fmaxf(b0, b1);
    float xb0 = expf(b0 - mj), xb1 = expf(b1 - mj);
    float dj = 1.0f / (xb0 + xb1);
    float vj0 = xb0 * dj, vj1 = xb1 * dj;

    #pragma unroll
    for (int it = 0; it < 10; it++) {
        float r0 = e00 + e01 + EPSF, r1 = e10 + e11 + EPSF;
        float c0 = e00 + e10 + EPSF, c1 = e01 + e11 + EPSF;
        float f0 = vi0 / r0, f1 = vi1 / r1;
        e00 *= f0; e01 *= f0; e10 *= f1; e11 *= f1;
        float g0 = vj0 / c0, g1 = vj1 / c1;
        e00 *= g0; e10 *= g0; e01 *= g1; e11 *= g1;
        float iv = 1.0f / (e00 + e01 + e10 + e11 + EPSF);
        e00 *= iv; e01 *= iv; e10 *= iv; e11 *= iv;
    }

    float wm = 0.0f;
    if (i != j) {
        float w = (i > j) ? W[i*N + j] : W[j*N + i];
        wm = 1.0f / (1.0f + expf(-w));
    } else {
        e00 = e01 = e10 = e11 = 0.0f;
    }
    e00 = fminf(fmaxf(e00, 0.0f), 1.0f);
    e01 = fminf(fmaxf(e01, 0.0f), 1.0f);
    e10 = fminf(fmaxf(e10, 0.0f), 1.0f);
    e11 = fminf(fmaxf(e11, 0.0f), 1.0f);

    g_C[0*N2 + p] = wm * e00 / (vi0 * vj0);
    g_C[1*N2 + p] = wm * e01 / (vi0 * vj1);
    g_C[2*N2 + p] = wm * e10 / (vi1 * vj0);
    g_C[3*N2 + p] = wm * e11 / (vi1 * vj1);
}

// ---------------- kernel 2: build padded 512x512 Laplacians ----------------
__global__ void __launch_bounds__(512, 1) k_build(const int* __restrict__ x,
                                                  const float* __restrict__ W) {
    __shared__ int sx[N];
    const int batch = blockIdx.x;
    const int tid   = threadIdx.x;
    float* Mb = g_M + (size_t)batch * N2;

    if (batch < BATCH) {
        for (int t = tid; t < N; t += 512) sx[t] = x[batch*N + t];
    }
    __syncthreads();

    int w = tid >> 5, lane = tid & 31;
    for (int r = w; r < N; r += 16) {
        if (r == N - 1) {
            for (int c = lane; c < N; c += 32) Mb[r*N + c] = (c == N-1) ? 1.0f : 0.0f;
            continue;
        }
        int i = r + 1;
        float sum = 0.0f;
        if (batch < BATCH) {
            int xi = sx[i];
            const float* p0 = g_C + (size_t)(xi*2) * N2 + (size_t)i * N;
            const float* p1 = p0 + N2;
            for (int j = lane; j < N; j += 32) {
                float v0 = p0[j], v1 = p1[j];
                float v = sx[j] ? v1 : v0;
                sum += v;
                int c = j - 1;
                if (j > 0 && c != r) Mb[r*N + c] = -v;
            }
        } else {
            for (int j = lane; j < N; j += 32) {
                float v = 0.0f;
                if (j != i) {
                    float wv = (i > j) ? W[i*N + j] : W[j*N + i];
                    v = 1.0f / (1.0f + expf(-wv));
                }
                sum += v;
                int c = j - 1;
                if (j > 0 && c != r) Mb[r*N + c] = -v;
            }
        }
        #pragma unroll
        for (int off = 16; off; off >>= 1) sum += __shfl_xor_sync(0xffffffffu, sum, off);
        if (lane == 0) { Mb[r*N + r] = sum; Mb[r*N + (N-1)] = 0.0f; }
    }
}

// ---------------- kernel 3: panel factor (D, L21, U12) ----------------
__global__ void __launch_bounds__(512, 1) k_panel(int kb) {
    __shared__ float sD[32*33];
    __shared__ float sDinv[32];
    const int mat = blockIdx.x;
    const int tid = threadIdx.x;
    float* Mb = g_M + (size_t)mat * N2;
    float* Lp = g_Lp + (size_t)mat * 32 * N;
    float* Up = g_Up + (size_t)mat * 32 * N;
    const int j0 = kb * 32, j1 = j0 + 32;
    const int m = N - j1;

    // warp 0: register LU of the 32x32 diagonal block (unpivoted; diag-dominant)
    if (tid < 32) {
        const int lane = tid;
        float v[32];
        const float4* rp = reinterpret_cast<const float4*>(&Mb[(size_t)(j0+lane)*N + j0]);
        #pragma unroll
        for (int q = 0; q < 8; q++) {
            float4 t4 = rp[q];
            v[4*q]=t4.x; v[4*q+1]=t4.y; v[4*q+2]=t4.z; v[4*q+3]=t4.w;
        }
        #pragma unroll
        for (int j = 0; j < 32; j++) {
            float diag = __shfl_sync(0xffffffffu, v[j], j);
            float l = v[j] * (1.0f / diag);
            #pragma unroll
            for (int c = j + 1; c < 32; c++) {
                float ujc = __shfl_sync(0xffffffffu, v[c], j);
                if (lane > j) v[c] -= l * ujc;
            }
            if (lane > j) v[j] = l;
        }
        float ld = logf(fabsf(v[lane]));
        #pragma unroll
        for (int off = 16; off; off >>= 1) ld += __shfl_xor_sync(0xffffffffu, ld, off);
        if (lane == 0) g_ld[mat*NPAN + kb] = ld;
        #pragma unroll
        for (int c = 0; c < 32; c++) sD[lane*33 + c] = v[c];
        sDinv[lane] = 1.0f / v[lane];
    }
    __syncthreads();

    if (tid < m) {
        // ---- L21 row r = j1+tid: solve l * U11 = A21_row; store NEGATED ----
        {
            const int r = j1 + tid;
            float a[32];
            const float4* rp = reinterpret_cast<const float4*>(&Mb[(size_t)r*N + j0]);
            #pragma unroll
            for (int q = 0; q < 8; q++) {
                float4 t4 = rp[q];
                a[4*q]=t4.x; a[4*q+1]=t4.y; a[4*q+2]=t4.z; a[4*q+3]=t4.w;
            }
            #pragma unroll
            for (int k = 0; k < 32; k++) {
                float acc = a[k];
                #pragma unroll
                for (int t = 0; t < k; t++) acc -= a[t] * sD[t*33 + k];
                a[k] = acc * sDinv[k];
            }
            #pragma unroll
            for (int k = 0; k < 32; k++) Lp[k*N + r] = -a[k];
        }
        // ---- U12 col c = j1+tid: forward substitution; store PLAIN ----
        {
            const int c = j1 + tid;
            float y[32];
            #pragma unroll
            for (int k = 0; k < 32; k++) y[k] = Mb[(size_t)(j0+k)*N + c];
            #pragma unroll
            for (int k = 1; k < 32; k++) {
                float acc = y[k];
                #pragma unroll
                for (int t = 0; t < k; t++) acc -= sD[k*33 + t] * y[t];
                y[k] = acc;
            }
            #pragma unroll
            for (int k = 0; k < 32; k++) Up[k*N + c] = y[k];
        }
    }
}

// ---------------- kernel 4: trailing update, one 128x128 tile per CTA ----------------
#define TLS 132            // smem row stride (u64 units for L, floats for U)
#define SMEM_UPD (32*TLS*8 + 32*TLS*4)

__global__ void __launch_bounds__(256) k_update(int kb) {
    extern __shared__ char smraw[];
    u64*   sLd = (u64*)smraw;                  // [k][rr] duplicated -L21
    float* sUu = (float*)(sLd + 32*TLS);       // [k][cc] U12

    const int mat = blockIdx.x;
    const int j1  = kb * 32 + 32;
    const int m   = N - j1;
    const int r0t = blockIdx.y * 128;
    const int c0t = blockIdx.z * 128;
    float* Mb = g_M + (size_t)mat * N2;
    const float* Lp = g_Lp + (size_t)mat * 32 * N;
    const float* Up = g_Up + (size_t)mat * 32 * N;
    const int tid = threadIdx.x;
    const int tx = tid & 15, ty = tid >> 4;

    // cooperative stage: L (negated, duplicated) and U
    for (int idx = tid; idx < 32*128; idx += 256) {
        int k = idx >> 7, q = idx & 127;
        float lv = (r0t + q < m) ? Lp[k*N + (j1 + r0t + q)] : 0.0f;
        sLd[k*TLS + q] = pack_dup(lv);
        float uv = (c0t + q < m) ? Up[k*N + (j1 + c0t + q)] : 0.0f;
        sUu[k*TLS + q] = uv;
    }
    __syncthreads();

    const int r0 = r0t + ty*8;          // relative to j1
    const int c0 = c0t + tx*8;
    if (r0 < m && c0 < m) {             // m multiple of 32 => full 8x8 valid
        const int ra = j1 + r0;         // absolute row
        const int ca = j1 + c0;         // absolute col
        u64 acc[8][4];
        #pragma unroll
        for (int ii = 0; ii < 8; ii++) {
            const ulonglong2* src = reinterpret_cast<const ulonglong2*>(
                &Mb[(size_t)(ra+ii)*N + ca]);
            ulonglong2 u0 = src[0], u1 = src[1];
            acc[ii][0]=u0.x; acc[ii][1]=u0.y; acc[ii][2]=u1.x; acc[ii][3]=u1.y;
        }
        #pragma unroll 8
        for (int k = 0; k < 32; k++) {
            const ulonglong2* ap = reinterpret_cast<const ulonglong2*>(&sLd[k*TLS + ty*8]);
            ulonglong2 a01 = ap[0], a23 = ap[1], a45 = ap[2], a67 = ap[3];
            const ulonglong2* bp = reinterpret_cast<const ulonglong2*>(&sUu[k*TLS + tx*8]);
            ulonglong2 b0 = bp[0], b1 = bp[1];
            acc[0][0]=ffma2(a01.x,b0.x,acc[0][0]);
            acc[0][1]=ffma2(a01.x,b0.y,acc[0][1]);
            acc[0][2]=ffma2(a01.x,b1.x,acc[0][2]);
            acc[0][3]=ffma2(a01.x,b1.y,acc[0][3]);
            acc[1][0]=ffma2(a01.y,b0.x,acc[1][0]);
            acc[1][1]=ffma2(a01.y,b0.y,acc[1][1]);
            acc[1][2]=ffma2(a01.y,b1.x,acc[1][2]);
            acc[1][3]=ffma2(a01.y,b1.y,acc[1][3]);
            acc[2][0]=ffma2(a23.x,b0.x,acc[2][0]);
            acc[2][1]=ffma2(a23.x,b0.y,acc[2][1]);
            acc[2][2]=ffma2(a23.x,b1.x,acc[2][2]);
            acc[2][3]=ffma2(a23.x,b1.y,acc[2][3]);
            acc[3][0]=ffma2(a23.y,b0.x,acc[3][0]);
            acc[3][1]=ffma2(a23.y,b0.y,acc[3][1]);
            acc[3][2]=ffma2(a23.y,b1.x,acc[3][2]);
            acc[3][3]=ffma2(a23.y,b1.y,acc[3][3]);
            acc[4][0]=ffma2(a45.x,b0.x,acc[4][0]);
            acc[4][1]=ffma2(a45.x,b0.y,acc[4][1]);
            acc[4][2]=ffma2(a45.x,b1.x,acc[4][2]);
            acc[4][3]=ffma2(a45.x,b1.y,acc[4][3]);
            acc[5][0]=ffma2(a45.y,b0.x,acc[5][0]);
            acc[5][1]=ffma2(a45.y,b0.y,acc[5][1]);
            acc[5][2]=ffma2(a45.y,b1.x,acc[5][2]);
            acc[5][3]=ffma2(a45.y,b1.y,acc[5][3]);
            acc[6][0]=ffma2(a67.x,b0.x,acc[6][0]);
            acc[6][1]=ffma2(a67.x,b0.y,acc[6][1]);
            acc[6][2]=ffma2(a67.x,b1.x,acc[6][2]);
            acc[6][3]=ffma2(a67.x,b1.y,acc[6][3]);
            acc[7][0]=ffma2(a67.y,b0.x,acc[7][0]);
            acc[7][1]=ffma2(a67.y,b0.y,acc[7][1]);
            acc[7][2]=ffma2(a67.y,b1.x,acc[7][2]);
            acc[7][3]=ffma2(a67.y,b1.y,acc[7][3]);
        }
        #pragma unroll
        for (int ii = 0; ii < 8; ii++) {
            ulonglong2* dst = reinterpret_cast<ulonglong2*>(&Mb[(size_t)(ra+ii)*N + ca]);
            ulonglong2 o0, o1;
            o0.x = acc[ii][0]; o0.y = acc[ii][1];
            o1.x = acc[ii][2]; o1.y = acc[ii][3];
            dst[0] = o0; dst[1] = o1;
        }
    }
}

// ---------------- kernel 5: combine ----------------
__global__ void k_final(const int* __restrict__ x, const float* __restrict__ Vc,
                        float* __restrict__ out) {
    __shared__ float red[256];
    int b = blockIdx.x, tid = threadIdx.x;
    float s = 0.0f;
    for (int i = tid; i < N; i += 256) {
        int xi = x[b*N + i];
        float a0 = Vc[2*i], a1 = Vc[2*i+1];
        float m = fmaxf(a0, a1);
        float lse = m + logf(expf(a0 - m) + expf(a1 - m));
        s += (xi ? a1 : a0) - lse;
    }
    red[tid] = s;
    __syncthreads();
    #pragma unroll
    for (int o = 128; o; o >>= 1) {
        if (tid < o) red[tid] += red[tid + o];
        __syncthreads();
    }
    if (tid == 0) {
        float ld = 0.0f;
        #pragma unroll
        for (int k = 0; k < NPAN; k++)
            ld += g_ld[b*NPAN + k] - g_ld[BATCH*NPAN + k];
        out[b] = red[0] + ld;
    }
}

// ---------------- launcher ----------------
extern "C" void kernel_launch(void* const* d_in, const int* in_sizes, int n_in,
                              void* d_out, int out_size) {
    const int* x = nullptr;
    const float* W = nullptr;
    const float* Vc = nullptr;
    const float* Ec = nullptr;
    for (int k = 0; k < n_in; k++) {
        switch (in_sizes[k]) {
            case BATCH * N:   x  = (const int*)d_in[k];   break;  // 65536
            case N * N:       W  = (const float*)d_in[k]; break;  // 262144
            case N * 2:       Vc = (const float*)d_in[k]; break;  // 1024
            case N * N * 4:   Ec = (const float*)d_in[k]; break;  // 1048576
        }
    }
    float* out = (float*)d_out;

    cudaFuncSetAttribute(k_update, cudaFuncAttributeMaxDynamicSharedMemorySize, SMEM_UPD);

    k_ipf<<<N2 / 256, 256>>>(W, Vc, Ec);
    k_build<<<NMAT, 512>>>(x, W);
    for (int kb = 0; kb < NPAN; kb++) {
        k_panel<<<NMAT, 512>>>(kb);
        int m = N - 32*(kb+1);
        if (m > 0) {
            int nt = (m + 127) / 128;
            dim3 grid(NMAT, nt, nt);
            k_update<<<grid, 256, SMEM_UPD>>>(kb);
        }
    }
    k_final<<<BATCH, 256>>>(x, Vc, out);
}